// round 15
// baseline (speedup 1.0000x reference)
#include <cuda_runtime.h>
#include <cuda_bf16.h>
#include <math.h>
#include <stdint.h>

// ------------------------- problem constants -------------------------
constexpr int kNI = 8192, kND = 4096, kNT = 12288, kD = 256, kH = 4, kDH = 64;
constexpr int kB = 8, kKP = 768;
constexpr int kEC = 65536, kEI = 32768, kEO = 32768, kEK = 8192;
constexpr long LXD = (long)kNT * kD;
constexpr long LPD = (long)kB * kKP * kD;
constexpr long KRVB = 8L * kNI * 256;          // bf16 elems per branch (K rels 0-3, V 4-7)
constexpr long SLEN = (long)kB * kH * kKP * kKP;

constexpr int O0 = 0;
constexpr int O1 = kNI;
constexpr int O2 = kNI + kND;
constexpr int O3 = 2 * kNI + kND;
constexpr int O4 = 2 * kNI + 2 * kND;
constexpr int CNT_TOT = O4 + kNT;

constexpr int BB0 = kEC;
constexpr int BB1 = BB0 + kEI;
constexpr int BB2 = BB1 + kEK;
constexpr int BB3 = BB2 + kEO;
constexpr int BB4 = BB3 + kEC;
constexpr int BB5 = BB4 + kEO;
constexpr int BB6 = BB5 + kEK;
constexpr int BB7 = BB6 + kEI;
constexpr int BB8 = BB7 + kEC;
constexpr int BB9 = BB8 + kEI;
constexpr int BB10 = BB9 + kEO;
constexpr int BB11 = BB10 + kEK;
constexpr int BB12 = BB11 + kNT;

typedef __nv_bfloat16 bf16;
typedef __nv_bfloat162 bf162;

// ------------------------- scratch -------------------------
struct Scratch {
    bf16 x[2][LXD], yF[2][LXD], agg[2][LXD];
    bf16 qb[2][LXD];                          // [branch][node][256] Q only
    bf16 krv[2][KRVB];                        // [relslot 0-7][node][256]
    bf16 S[2][SLEN];
    bf16 xp[2][LPD], qkvp[2][3 * LPD], oh[2][LPD], yb[2][LPD], ga[2][LPD];
    bf16 vT[2][(long)kB * kH * 64 * kKP];     // V transposed [b][h][dh][key]
    bf16 pWq[8L * 256 * 256];                 // [combo*2+t][n][k] Q weights
    bf16 pTw[768L * 256];
    bf16 pComb[128L * 64 * 256];              // [(c*8+slot)*4+h][o=64][k=256]
    bf16 pWo[8L * 256 * 256];
    bf16 pTwo[256L * 256];
    float hv[2 * kNT], sc[2 * kNT];
    float sv[2 * kB * kKP];
    int   si[2 * kB * kKP];
    float u[2 * kB * 512];
    float up[2 * kB * 6 * 512];
    int rpf0[2][kNI + 1], rpf1[2][kND + 1], rpr0[2][kNI + 1], rpr1[2][kND + 1], rph[2][kNT + 1];
    int ef0[2][kEC + kEI + kEK], ef1[2][kEO], er0[2][kEC + kEO + kEK], er1[2][kEI];
    int eh[2][kEC + kEI + kEO + kEK + kNT];
    int cnt[CNT_TOT], cur[CNT_TOT];
};
__device__ Scratch SC;

// ------------------------- reductions -------------------------
__device__ __forceinline__ float wsum(float v) {
#pragma unroll
    for (int o = 16; o; o >>= 1) v += __shfl_xor_sync(0xffffffffu, v, o);
    return v;
}
__device__ __forceinline__ float bsum(float v) {
    __shared__ float sh[32];
    int lane = threadIdx.x & 31, w = threadIdx.x >> 5;
    v = wsum(v);
    if (!lane) sh[w] = v;
    __syncthreads();
    int nw = blockDim.x >> 5;
    float s = (threadIdx.x < nw) ? sh[threadIdx.x] : 0.f;
    if (w == 0) s = wsum(s);
    if (threadIdx.x == 0) sh[0] = s;
    __syncthreads();
    float r = sh[0];
    __syncthreads();
    return r;
}
__device__ __forceinline__ float bmax(float v) {
    __shared__ float sh[32];
    int lane = threadIdx.x & 31, w = threadIdx.x >> 5;
#pragma unroll
    for (int o = 16; o; o >>= 1) v = fmaxf(v, __shfl_xor_sync(0xffffffffu, v, o));
    if (!lane) sh[w] = v;
    __syncthreads();
    int nw = blockDim.x >> 5;
    float s = (threadIdx.x < nw) ? sh[threadIdx.x] : -INFINITY;
    if (w == 0)
#pragma unroll
        for (int o = 16; o; o >>= 1) s = fmaxf(s, __shfl_xor_sync(0xffffffffu, s, o));
    if (threadIdx.x == 0) sh[0] = s;
    __syncthreads();
    float r = sh[0];
    __syncthreads();
    return r;
}

// ------------------------- bf16 mma helpers -------------------------
__device__ __forceinline__ void mma_bf16(float* c, const uint32_t* a,
                                         uint32_t b0, uint32_t b1) {
    asm volatile(
        "mma.sync.aligned.m16n8k16.row.col.f32.bf16.bf16.f32 "
        "{%0,%1,%2,%3}, {%4,%5,%6,%7}, {%8,%9}, {%0,%1,%2,%3};"
        : "+f"(c[0]), "+f"(c[1]), "+f"(c[2]), "+f"(c[3])
        : "r"(a[0]), "r"(a[1]), "r"(a[2]), "r"(a[3]), "r"(b0), "r"(b1));
}
__device__ __forceinline__ void cpa16(void* dst, const void* src) {
    unsigned d = (unsigned)__cvta_generic_to_shared(dst);
    asm volatile("cp.async.cg.shared.global [%0], [%1], 16;\n" :: "r"(d), "l"(src));
}
#define CP_COMMIT() asm volatile("cp.async.commit_group;\n" ::: "memory")
#define CP_WAIT1()  asm volatile("cp.async.wait_group 1;\n" ::: "memory")
#define CP_WAIT0()  asm volatile("cp.async.wait_group 0;\n" ::: "memory")

// ------------------------- generic bf16 GEMM (cp.async pipelined) --------
template <int BN>
__global__ void __launch_bounds__(256, 2) hgemm_k(
    const bf16* __restrict__ A, int lda, long A2, long Ab, long Ah,
    const bf16* __restrict__ Bm, int ldb, long B2, long Bb, long Bh,
    bf16* __restrict__ C, int ldc, long C2, long Cb, long Ch,
    const bf16* __restrict__ Add, int ldadd, const bf16* __restrict__ Add2,
    const float* __restrict__ gptr,
    int Kdim, int ZH, int ZT, float alpha, int mode,
    unsigned zmask, long Aalt, int Malt, int Mdef, long Valt, int zsplit)
{
    constexpr int BM = 128, BK = 32;
    constexpr int STR = 40;
    constexpr int TN = (BN == 128) ? 8 : 4;
    extern __shared__ bf16 smh_[];
    bf16* As = smh_;
    bf16* Bs = smh_ + 2 * BM * STR;

    int z = blockIdx.z;
    int z2 = z / ZT, rz = z - z2 * ZT;
    int zb = rz / ZH, zh = rz - zb * ZH;
    int msk = (zmask >> zb) & 1;
    int Mz = msk ? Malt : Mdef;
    int m0 = blockIdx.x * BM;
    if (m0 >= Mz) return;
    const bf16* Ax = A + z2 * A2 + zb * Ab + zh * Ah + (msk ? Aalt : 0)
                       + (zb >= zsplit ? Valt : 0);
    const bf16* Bx = Bm + z2 * B2 + zb * Bb + zh * Bh;
    long coff = z2 * C2 + zb * Cb + zh * Ch;
    C += coff;
    if (Add)  Add  += coff;
    if (Add2) Add2 += coff;
    int n0 = blockIdx.y * BN;
    int tid = threadIdx.x, lane = tid & 31, warp = tid >> 5;
    int wm = warp >> 1, wn = warp & 1;
    int g = lane >> 2, tg = lane & 3;

    float acc[2][TN][4];
#pragma unroll
    for (int i = 0; i < 2; i++)
#pragma unroll
        for (int j = 0; j < TN; j++)
#pragma unroll
            for (int q = 0; q < 4; q++) acc[i][j][q] = 0.f;

    int nt = Kdim / BK;

#define ISSUE(K0, Sg) do {                                                     \
        bf16* Ad = As + (Sg) * BM * STR;                                       \
        _Pragma("unroll")                                                      \
        for (int q = 0; q < 2; q++) {                                          \
            int f = tid + q * 256, row = f >> 2, kc = (f & 3) * 8;             \
            cpa16(Ad + row * STR + kc,                                         \
                  Ax + (long)(m0 + row) * lda + (K0) + kc);                    \
        }                                                                      \
        bf16* Bd = Bs + (Sg) * BN * STR;                                       \
        _Pragma("unroll")                                                      \
        for (int q = 0; q < BN / 64; q++) {                                    \
            int f = tid + q * 256, row = f >> 2, kc = (f & 3) * 8;             \
            cpa16(Bd + row * STR + kc,                                         \
                  Bx + (long)(n0 + row) * ldb + (K0) + kc);                    \
        }                                                                      \
    } while (0)

    ISSUE(0, 0);
    CP_COMMIT();

    for (int t = 0; t < nt; t++) {
        if (t + 1 < nt) {
            ISSUE((t + 1) * BK, (t + 1) & 1);
            CP_COMMIT();
            CP_WAIT1();
        } else {
            CP_WAIT0();
        }
        __syncthreads();
        const bf16* Ap = As + (size_t)(t & 1) * BM * STR;
        const bf16* Bp = Bs + (size_t)(t & 1) * BN * STR;
#pragma unroll
        for (int k16 = 0; k16 < 2; k16++) {
            int kb = k16 * 16;
            uint32_t a[2][4];
#pragma unroll
            for (int tm = 0; tm < 2; tm++) {
                int mr = wm * 32 + tm * 16;
                a[tm][0] = *(const uint32_t*)(Ap + (mr + g) * STR + kb + 2 * tg);
                a[tm][1] = *(const uint32_t*)(Ap + (mr + 8 + g) * STR + kb + 2 * tg);
                a[tm][2] = *(const uint32_t*)(Ap + (mr + g) * STR + kb + 2 * tg + 8);
                a[tm][3] = *(const uint32_t*)(Ap + (mr + 8 + g) * STR + kb + 2 * tg + 8);
            }
#pragma unroll
            for (int tn = 0; tn < TN; tn++) {
                int nc = wn * (TN * 8) + tn * 8 + g;
                uint32_t b0 = *(const uint32_t*)(Bp + nc * STR + kb + 2 * tg);
                uint32_t b1 = *(const uint32_t*)(Bp + nc * STR + kb + 2 * tg + 8);
#pragma unroll
                for (int tm = 0; tm < 2; tm++)
                    mma_bf16(acc[tm][tn], a[tm], b0, b1);
            }
        }
        __syncthreads();
    }
#undef ISSUE

    float gg = 1.f;
    if (mode == 1 || mode == 3) gg = 1.f / (1.f + expf(-gptr[zb]));
#pragma unroll
    for (int tm = 0; tm < 2; tm++) {
        long row0 = m0 + wm * 32 + tm * 16 + g;
#pragma unroll
        for (int tn = 0; tn < TN; tn++) {
            long col = n0 + wn * (TN * 8) + tn * 8 + tg * 2;
#pragma unroll
            for (int half = 0; half < 2; half++) {
                long r = row0 + half * 8;
                float vx = alpha * acc[tm][tn][half * 2 + 0];
                float vy = alpha * acc[tm][tn][half * 2 + 1];
                if (mode == 1) {
                    float2 ad = __bfloat1622float2(*(const bf162*)(Add + r * ldadd + col));
                    vx = gg * vx + (1.f - gg) * ad.x;
                    vy = gg * vy + (1.f - gg) * ad.y;
                } else if (mode == 2) {
                    float2 ad = __bfloat1622float2(*(const bf162*)(Add + r * ldadd + col));
                    vx += ad.x; vy += ad.y;
                } else if (mode == 3) {
                    float2 ad = __bfloat1622float2(*(const bf162*)(Add + r * ldadd + col));
                    float2 a2 = __bfloat1622float2(*(const bf162*)(Add2 + r * ldadd + col));
                    vx = 0.5f * (gg * vx + (1.f - gg) * ad.x) + 0.5f * a2.x;
                    vy = 0.5f * (gg * vy + (1.f - gg) * ad.y) + 0.5f * a2.y;
                    vx = vx > 0.f ? vx : 0.f;
                    vy = vy > 0.f ? vy : 0.f;
                }
                *(bf162*)(C + r * ldc + col) = __floats2bfloat162_rn(vx, vy);
            }
        }
    }
}

// ---------------- Krel/Vrel from combined weights: krv = x @ pComb -----------
// grid (96, 1, 16): z -> branch(2) x kv(2) x head(4). K=256 single-shot smem.
__global__ void __launch_bounds__(256) krel_k(Scratch* sp, int combo, int dir) {
    constexpr int SA = 264;
    extern __shared__ bf16 smk_[];
    bf16* As = smk_;                 // [128][SA]
    bf16* Bs = smk_ + 128 * SA;      // [4][64][SA]
    int z = blockIdx.z;
    int branch = z >> 3, rem = z & 7;
    int kv = rem >> 2, h = rem & 3;
    int m0 = blockIdx.x * 128;
    int tid = threadIdx.x;
    const bf16* Aptr = sp->x[branch] + (long)m0 * 256;
#pragma unroll
    for (int q = 0; q < 16; q++) {
        int f = tid + q * 256, row = f >> 5, kc = (f & 31) * 8;
        cpa16(As + row * SA + kc, Aptr + (long)row * 256 + kc);
    }
#pragma unroll
    for (int q = 0; q < 32; q++) {
        int f = tid + q * 256;
        int r = f >> 11, row = (f >> 5) & 63, kc = (f & 31) * 8;
        cpa16(Bs + (r * 64 + row) * SA + kc,
              sp->pComb + ((long)(combo * 8 + kv * 4 + r) * 4 + h) * 16384
                        + (long)row * 256 + kc);
    }
    CP_COMMIT(); CP_WAIT0();
    __syncthreads();
    int lane = tid & 31, warp = tid >> 5;
    int wm = warp >> 1, wn = warp & 1;
    int g = lane >> 2, tg = lane & 3;
    bool validR[4];
#pragma unroll
    for (int r = 0; r < 4; r++) {
        int srcData = (dir == 0) ? (r == 1) : (r == 2);
        validR[r] = srcData ? (m0 >= 8192) : (m0 < 8192);
    }
    float acc[4][2][4][4];
#pragma unroll
    for (int r = 0; r < 4; r++)
#pragma unroll
        for (int i = 0; i < 2; i++)
#pragma unroll
            for (int j = 0; j < 4; j++)
#pragma unroll
                for (int q = 0; q < 4; q++) acc[r][i][j][q] = 0.f;
#pragma unroll
    for (int k16 = 0; k16 < 16; k16++) {
        int kb = k16 * 16;
        uint32_t a[2][4];
#pragma unroll
        for (int tm = 0; tm < 2; tm++) {
            int mr = wm * 32 + tm * 16;
            a[tm][0] = *(const uint32_t*)(As + (mr + g) * SA + kb + 2 * tg);
            a[tm][1] = *(const uint32_t*)(As + (mr + 8 + g) * SA + kb + 2 * tg);
            a[tm][2] = *(const uint32_t*)(As + (mr + g) * SA + kb + 2 * tg + 8);
            a[tm][3] = *(const uint32_t*)(As + (mr + 8 + g) * SA + kb + 2 * tg + 8);
        }
#pragma unroll
        for (int r = 0; r < 4; r++) {
            if (!validR[r]) continue;
            const bf16* Bp = Bs + r * 64 * SA;
#pragma unroll
            for (int tn = 0; tn < 4; tn++) {
                int nc = wn * 32 + tn * 8 + g;
                uint32_t b0 = *(const uint32_t*)(Bp + nc * SA + kb + 2 * tg);
                uint32_t b1 = *(const uint32_t*)(Bp + nc * SA + kb + 2 * tg + 8);
                mma_bf16(acc[r][0][tn], a[0], b0, b1);
                mma_bf16(acc[r][1][tn], a[1], b0, b1);
            }
        }
    }
#pragma unroll
    for (int r = 0; r < 4; r++) {
        if (!validR[r]) continue;
        int srcData = (dir == 0) ? (r == 1) : (r == 2);
        int slot = kv * 4 + r;
        long crow0 = m0 - (srcData ? 8192 : 0);
        bf16* C = sp->krv[branch] + ((long)slot * kNI + crow0) * 256 + h * 64;
#pragma unroll
        for (int tm = 0; tm < 2; tm++) {
            long row0 = wm * 32 + tm * 16 + g;
#pragma unroll
            for (int tn = 0; tn < 4; tn++) {
                long col = wn * 32 + tn * 8 + tg * 2;
#pragma unroll
                for (int half = 0; half < 2; half++) {
                    long rr = row0 + half * 8;
                    *(bf162*)(C + rr * 256 + col) =
                        __floats2bfloat162_rn(acc[r][tm][tn][half * 2 + 0],
                                              acc[r][tm][tn][half * 2 + 1]);
                }
            }
        }
    }
}

// -------------------- combined-weight packing: pComb = Wk/Wv @ rel -----------
// grid 128: b -> c(4) x slot(8) x h(4). fp32 math, bf16 store.
__global__ void pack_comb_k(const float* __restrict__ Wk, const float* __restrict__ Wv,
                            const float* __restrict__ arel, const float* __restrict__ mrel,
                            Scratch* sp) {
    int b = blockIdx.x;
    int c = b >> 5, slot = (b >> 2) & 7, h = b & 3;
    int kv = slot >> 2, r = slot & 3, dir = c & 1;
    int t = (dir == 0) ? (r == 1) : (r == 2);
    const float* W = (kv ? Wv : Wk) + ((long)c * 2 + t) * 65536;
    const float* rel = (kv ? mrel : arel) + (((long)c * 4 + r) * 4 + h) * 4096;
    extern __shared__ float smf_[];
    float* Ws = smf_;                // [256][65]
    float* Rl = smf_ + 256 * 65;     // [64][64]
    int tid = threadIdx.x;
    for (int j = 0; j < 64; j++) Ws[tid * 65 + j] = W[(long)tid * 256 + h * 64 + j];
    for (int q = tid; q < 4096; q += 256) Rl[q] = rel[q];
    __syncthreads();
    float wrow[64];
#pragma unroll
    for (int j = 0; j < 64; j++) wrow[j] = Ws[tid * 65 + j];
    bf16* out = sp->pComb + (long)b * 16384;
    for (int o = 0; o < 64; o++) {
        float accv = 0.f;
#pragma unroll
        for (int j = 0; j < 64; j++) accv += wrow[j] * Rl[j * 64 + o];
        out[o * 256 + tid] = __float2bfloat16(accv);
    }
}

// ------------------------- fused weight packing (bf16, [n][k]) -------
constexpr long PWq = 8L * 65536;
constexpr long PT  = 768L * 256;
constexpr long PO  = 8L * 65536;
constexpr long P2  = 65536;
__global__ void pack_all_k(const float* __restrict__ Wq, const float* __restrict__ tWq,
                           const float* __restrict__ tWk, const float* __restrict__ tWv,
                           const float* __restrict__ Wo, const float* __restrict__ tWo,
                           Scratch* sp) {
    long i = (long)blockIdx.x * 256 + threadIdx.x;
    if (i < PWq) {
        long c = i / 65536, rm = i % 65536;
        int n = (int)(rm / 256), k = (int)(rm % 256);
        sp->pWq[i] = __float2bfloat16(Wq[c * 65536 + (long)k * 256 + n]);
    } else if (i < PWq + PT) {
        long j = i - PWq;
        int n = (int)(j / 256), k = (int)(j % 256);
        int sel = n >> 8, nn = n & 255;
        const float* W = (sel == 0) ? tWq : (sel == 1) ? tWk : tWv;
        sp->pTw[j] = __float2bfloat16(W[(long)k * 256 + nn]);
    } else if (i < PWq + PT + PO) {
        long j = i - PWq - PT;
        long c = j / 65536, rm = j % 65536;
        int n = (int)(rm / 256), k = (int)(rm % 256);
        sp->pWo[j] = __float2bfloat16(Wo[c * 65536 + (long)k * 256 + n]);
    } else if (i < PWq + PT + PO + P2) {
        long j = i - PWq - PT - PO;
        int n = (int)(j / 256), k = (int)(j % 256);
        sp->pTwo[j] = __float2bfloat16(tWo[(long)k * 256 + n]);
    }
}

// ------------------------- elementwise -------------------------
__global__ void assemble_x_k(const float* __restrict__ xi0, const float* __restrict__ xd0,
                             const float* __restrict__ xi1, const float* __restrict__ xd1,
                             Scratch* sp) {
    long i = ((long)blockIdx.x * blockDim.x + threadIdx.x) * 4;
    if (i < 2 * LXD) {
        const long T1 = (long)kNI * kD;
        int br = i >= LXD;
        long loc = i - (long)br * LXD;
        const float* xi = br ? xi1 : xi0;
        const float* xd = br ? xd1 : xd0;
        float4 v = (loc < T1) ? *(const float4*)(xi + loc) : *(const float4*)(xd + (loc - T1));
        bf162 h0 = __floats2bfloat162_rn(v.x, v.y);
        bf162 h1 = __floats2bfloat162_rn(v.z, v.w);
        *(bf162*)(&sp->x[0][0] + i) = h0;
        *(bf162*)(&sp->x[0][0] + i + 2) = h1;
    }
}
__global__ void vtrans_k(Scratch* sp) {
    long i = (long)blockIdx.x * blockDim.x + threadIdx.x;
    if (i >= 2L * kB * kH * 64 * kKP) return;
    int key = (int)(i % kKP);
    long r = i / kKP;
    int dh = (int)(r & 63);
    long r2 = r >> 6;
    int h = (int)(r2 & 3);
    long r3 = r2 >> 2;
    int b = (int)(r3 & 7);
    int br = (int)(r3 >> 3);
    sp->vT[br][(((long)b * 4 + h) * 64 + dh) * kKP + key] =
        sp->qkvp[br][((long)b * kKP + key) * 768 + 512 + h * 64 + dh];
}

// ------------------------- fused CSR construction -------------------------
struct Slot { int idx; int ent; int arr; };
__device__ __forceinline__ Slot decode_slot(
    int i, const int* rc, const int* cc, const int* ri, const int* ci,
    const int* ro, const int* co, const int* rk, const int* ck)
{
    Slot s;
    if (i < BB0)       { s.idx = O0 + cc[i];            s.ent = (0 << 16) | rc[i];            s.arr = 0; }
    else if (i < BB1)  { int j = i - BB0;  s.idx = O0 + ci[j]; s.ent = (1 << 16) | ri[j];     s.arr = 0; }
    else if (i < BB2)  { int j = i - BB1;  s.idx = O0 + ck[j]; s.ent = (3 << 16) | rk[j];     s.arr = 0; }
    else if (i < BB3)  { int j = i - BB2;  s.idx = O1 + co[j]; s.ent = (2 << 16) | ro[j];     s.arr = 1; }
    else if (i < BB4)  { int j = i - BB3;  s.idx = O2 + rc[j]; s.ent = (0 << 16) | cc[j];     s.arr = 2; }
    else if (i < BB5)  { int j = i - BB4;  s.idx = O2 + ro[j]; s.ent = (2 << 16) | co[j];     s.arr = 2; }
    else if (i < BB6)  { int j = i - BB5;  s.idx = O2 + rk[j]; s.ent = (3 << 16) | ck[j];     s.arr = 2; }
    else if (i < BB7)  { int j = i - BB6;  s.idx = O3 + ri[j]; s.ent = (1 << 16) | ci[j];     s.arr = 3; }
    else if (i < BB8)  { int j = i - BB7;  s.idx = O4 + cc[j]; s.ent = rc[j];                 s.arr = 4; }
    else if (i < BB9)  { int j = i - BB8;  s.idx = O4 + ci[j]; s.ent = ri[j] + kNI;           s.arr = 4; }
    else if (i < BB10) { int j = i - BB9;  s.idx = O4 + co[j] + kNI; s.ent = ro[j];           s.arr = 4; }
    else               { int j = i - BB10; s.idx = O4 + ck[j]; s.ent = rk[j];                 s.arr = 4; }
    return s;
}

__global__ void csr_count_k(Scratch* sp, const int* rc, const int* cc,
                            const int* ri, const int* ci, const int* ro, const int* co,
                            const int* rk, const int* ck) {
    int i = blockIdx.x * blockDim.x + threadIdx.x;
    if (i < BB11) {
        Slot s = decode_slot(i, rc, cc, ri, ci, ro, co, rk, ck);
        atomicAdd(&sp->cnt[s.idx], 1);
    }
}
__global__ void csr_scan_k(Scratch* sp, int br) {
    __shared__ int sh[1024];
    int region = blockIdx.x, t = threadIdx.x;
    int off, n, extra = 0;
    int* rp;
    switch (region) {
        case 0: off = O0; n = kNI; rp = sp->rpf0[br]; break;
        case 1: off = O1; n = kND; rp = sp->rpf1[br]; break;
        case 2: off = O2; n = kNI; rp = sp->rpr0[br]; break;
        case 3: off = O3; n = kND; rp = sp->rpr1[br]; break;
        default: off = O4; n = kNT; rp = sp->rph[br]; extra = 1; break;
    }
    int c = (n + 1023) >> 10;
    int beg = t * c, end = min(beg + c, n);
    int s = 0;
    for (int i = beg; i < end; i++) s += sp->cnt[off + i] + extra;
    sh[t] = s;
    __syncthreads();
    for (int o = 1; o < 1024; o <<= 1) {
        int v = (t >= o) ? sh[t - o] : 0;
        __syncthreads();
        sh[t] += v;
        __syncthreads();
    }
    int run = t ? sh[t - 1] : 0;
    for (int i = beg; i < end; i++) {
        int cv = sp->cnt[off + i];
        sp->cnt[off + i] = 0;
        rp[i] = run;
        sp->cur[off + i] = run;
        run += cv + extra;
    }
    if (t == 1023) rp[n] = sh[1023];
}
__global__ void csr_fill_k(Scratch* sp, int br, const int* rc, const int* cc,
                           const int* ri, const int* ci, const int* ro, const int* co,
                           const int* rk, const int* ck) {
    int i = blockIdx.x * blockDim.x + threadIdx.x;
    if (i >= BB12) return;
    if (i < BB11) {
        Slot s = decode_slot(i, rc, cc, ri, ci, ro, co, rk, ck);
        int pos = atomicAdd(&sp->cur[s.idx], 1);
        switch (s.arr) {
            case 0: sp->ef0[br][pos] = s.ent; break;
            case 1: sp->ef1[br][pos] = s.ent; break;
            case 2: sp->er0[br][pos] = s.ent; break;
            case 3: sp->er1[br][pos] = s.ent; break;
            default: sp->eh[br][pos] = s.ent; break;
        }
    } else {
        int node = i - BB11;
        int pos = atomicAdd(&sp->cur[O4 + node], 1);
        sp->eh[br][pos] = node;
    }
}

// ------------------- HGT softmax aggregation (4-edge ILP) --------------
__global__ void hgt_agg_k(Scratch* sp, int dir, const float* __restrict__ prel) {
    int nb = blockIdx.x;
    int branch = nb >= kNT;
    int node = nb - branch * kNT;
    const int *rp, *ent; int idx;
    if (dir == 0) {
        if (node < kNI) { rp = sp->rpf0[branch]; ent = sp->ef0[branch]; idx = node; }
        else            { rp = sp->rpf1[branch]; ent = sp->ef1[branch]; idx = node - kNI; }
    } else {
        if (node < kNI) { rp = sp->rpr0[branch]; ent = sp->er0[branch]; idx = node; }
        else            { rp = sp->rpr1[branch]; ent = sp->er1[branch]; idx = node - kNI; }
    }
    int h = threadIdx.x >> 5, lane = threadIdx.x & 31;
    long hoff = h * 64 + 2 * lane;
    float2 qq = __bfloat1622float2(
        *(const bf162*)(sp->qb[branch] + (long)node * 256 + hoff));
    float q0 = qq.x, q1 = qq.y;
    const bf16* krv = sp->krv[branch];
    float pr0 = prel[0 * kH + h], pr1 = prel[1 * kH + h];
    float pr2 = prel[2 * kH + h], pr3 = prel[3 * kH + h];
    int s = rp[idx], eend = rp[idx + 1];
    float m = -INFINITY, den = 0.f, a0 = 0.f, a1 = 0.f;
    int e = s;
    for (; e + 3 < eend; e += 4) {
        int pk[4], rr[4], ss[4];
#pragma unroll
        for (int u = 0; u < 4; u++) {
            pk[u] = ent[e + u];
            rr[u] = pk[u] >> 16;
            ss[u] = pk[u] & 0xffff;
        }
        float2 kk[4], vv[4];
#pragma unroll
        for (int u = 0; u < 4; u++) {
            kk[u] = __bfloat1622float2(
                *(const bf162*)(krv + ((long)rr[u] * kNI + ss[u]) * 256 + hoff));
            vv[u] = __bfloat1622float2(
                *(const bf162*)(krv + ((long)(rr[u] + 4) * kNI + ss[u]) * 256 + hoff));
        }
        float d[4];
#pragma unroll
        for (int u = 0; u < 4; u++) d[u] = q0 * kk[u].x + q1 * kk[u].y;
#pragma unroll
        for (int o = 16; o; o >>= 1) {
#pragma unroll
            for (int u = 0; u < 4; u++)
                d[u] += __shfl_xor_sync(0xffffffffu, d[u], o);
        }
        float sc4[4];
#pragma unroll
        for (int u = 0; u < 4; u++) {
            int r = rr[u];
            float pr = (r == 0) ? pr0 : (r == 1) ? pr1 : (r == 2) ? pr2 : pr3;
            sc4[u] = d[u] * pr * 0.125f;
        }
        float mn = fmaxf(fmaxf(m, fmaxf(sc4[0], sc4[1])), fmaxf(sc4[2], sc4[3]));
        float cc = expf(m - mn);
        float w0 = expf(sc4[0] - mn), w1 = expf(sc4[1] - mn);
        float w2 = expf(sc4[2] - mn), w3 = expf(sc4[3] - mn);
        den = den * cc + w0 + w1 + w2 + w3;
        a0 = a0 * cc + w0 * vv[0].x + w1 * vv[1].x + w2 * vv[2].x + w3 * vv[3].x;
        a1 = a1 * cc + w0 * vv[0].y + w1 * vv[1].y + w2 * vv[2].y + w3 * vv[3].y;
        m = mn;
    }
    for (; e < eend; e++) {
        int pk = ent[e];
        int r = pk >> 16, src = pk & 0xffff;
        float2 kk = __bfloat1622float2(
            *(const bf162*)(krv + ((long)r * kNI + src) * 256 + hoff));
        float2 vv = __bfloat1622float2(
            *(const bf162*)(krv + ((long)(r + 4) * kNI + src) * 256 + hoff));
        float d0 = q0 * kk.x + q1 * kk.y;
        d0 = wsum(d0);
        float pr = (r == 0) ? pr0 : (r == 1) ? pr1 : (r == 2) ? pr2 : pr3;
        float sc2 = d0 * pr * 0.125f;
        float mn = fmaxf(m, sc2);
        float cc = expf(m - mn), w = expf(sc2 - mn);
        den = den * cc + w;
        a0 = a0 * cc + w * vv.x;
        a1 = a1 * cc + w * vv.y;
        m = mn;
    }
    float inv = 1.f / (den + 1e-16f);
    float r0 = a0 * inv, r1 = a1 * inv;
    float g0 = 0.5f * r0 * (1.f + erff(r0 * 0.7071067811865475f));
    float g1 = 0.5f * r1 * (1.f + erff(r1 * 0.7071067811865475f));
    *(bf162*)(sp->agg[branch] + (long)node * kD + hoff) = __floats2bfloat162_rn(g0, g1);
}

// ------------------------- pooling -------------------------
__global__ void hv_k(Scratch* sp, const float* __restrict__ pw) {
    int nb = blockIdx.x * 8 + (threadIdx.x >> 5);
    int lane = threadIdx.x & 31;
    if (nb >= 2 * kNT) return;
    const bf16* x = &sp->x[0][0];
    float s = 0.f;
    for (int d = lane * 2; d < kD; d += 64) {
        float2 v = __bfloat1622float2(*(const bf162*)(x + (long)nb * kD + d));
        s += v.x * pw[d] + v.y * pw[d + 1];
    }
    s = wsum(s);
    if (!lane) sp->hv[nb] = s;
}
__global__ void gat_score_k(Scratch* sp, const float* __restrict__ att,
                            const float* __restrict__ bias) {
    int i = blockIdx.x * blockDim.x + threadIdx.x;
    if (i >= 2 * kNT) return;
    int branch = i / kNT, ii = i - branch * kNT;
    const int* rp = sp->rph[branch];
    const int* ent = sp->eh[branch];
    float A0 = att[0], A1 = att[1];
    float hi = sp->hv[i];
    int s = rp[ii], e1 = rp[ii + 1];
    float m = -INFINITY, den = 0.f, acc = 0.f;
    int hb = branch * kNT;
    for (int e = s; e < e1; e++) {
        int src = ent[e] & 0xffff;
        float hs = sp->hv[hb + src];
        float ee = A0 * hs + A1 * hi;
        ee = ee >= 0.f ? ee : 0.2f * ee;
        float mn = fmaxf(m, ee);
        float c = expf(m - mn), w = expf(ee - mn);
        den = den * c + w;
        acc = acc * c + w * hs;
        m = mn;
    }
    sp->sc[i] = acc / (den + 1e-16f) + bias[0];
}

__global__ void topk_sort_k(Scratch* sp) {
    int bi = blockIdx.x;
    int branch = bi >> 3, b = bi & 7;
    int t = threadIdx.x;
    const float* sc = sp->sc + branch * kNT;
    __shared__ float v[2048];
    __shared__ int ix[2048];
    for (int p = t; p < 2048; p += 1024) {
        float val = -INFINITY;
        if (p < 1536) {
            int node = p < 1024 ? b * 1024 + p : kNI + b * 512 + (p - 1024);
            val = sc[node];
        }
        v[p] = val;
        ix[p] = p;
    }
    __syncthreads();
    for (int k = 2; k <= 2048; k <<= 1)
        for (int j = k >> 1; j > 0; j >>= 1) {
#pragma unroll
            for (int pass = 0; pass < 2; pass++) {
                int i = t + pass * 1024;
                int l = i ^ j;
                if (l > i) {
                    bool up = ((i & k) == 0);
                    float vi = v[i], vl = v[l];
                    int ii = ix[i], il = ix[l];
                    bool before = (vi > vl) || (vi == vl && ii < il);
                    if (up != before) {
                        v[i] = vl; v[l] = vi;
                        ix[i] = il; ix[l] = ii;
                    }
                }
            }
            __syncthreads();
        }
    if (t < kKP) {
        sp->sv[bi * kKP + t] = v[t];
        sp->si[bi * kKP + t] = ix[t];
    }
}
__global__ void gather_k(Scratch* sp) {
    int q = blockIdx.x, bi = blockIdx.y, d = threadIdx.x;
    int branch = bi >> 3, b = bi & 7;
    int j = sp->si[bi * kKP + q];
    float tv = tanhf(sp->sv[bi * kKP + q]);
    int node = j < 1024 ? b * 1024 + j : kNI + b * 512 + (j - 1024);
    float vv = __bfloat162float(sp->x[branch][(long)node * kD + d]) * tv;
    sp->xp[branch][((long)(b * kKP + q)) * kD + d] = __float2bfloat16(vv);
}

// ------------------------- transformer pieces -------------------------
__global__ void softmax_k(bf16* __restrict__ S) {
    long row = blockIdx.x;
    bf16* p = S + row * kKP;
    int t = threadIdx.x;
    float v0 = __bfloat162float(p[t]);
    float v1 = __bfloat162float(p[t + 256]);
    float v2 = __bfloat162float(p[t + 512]);
    float m = bmax(fmaxf(v0, fmaxf(v1, v2)));
    v0 = expf(v0 - m); v1 = expf(v1 - m); v2 = expf(v2 - m);
    float s = bsum(v0 + v1 + v2);
    float inv = 1.f / s;
    p[t] = __float2bfloat16(v0 * inv);
    p[t + 256] = __float2bfloat16(v1 * inv);
    p[t + 512] = __float2bfloat16(v2 * inv);
}
__global__ void ln_k(const bf16* __restrict__ y, const float* __restrict__ g,
                     const float* __restrict__ bta, bf16* __restrict__ out) {
    long row = blockIdx.x;
    int d = threadIdx.x;
    float v = __bfloat162float(y[row * kD + d]);
    float mu = bsum(v) * (1.f / kD);
    float df = v - mu;
    float var = bsum(df * df) * (1.f / kD);
    out[row * kD + d] = __float2bfloat16(g[d] * df * rsqrtf(var + 1e-5f) + bta[d]);
}
__global__ void featsum_part_k(Scratch* sp) {
    int bi = blockIdx.x, ch = blockIdx.y, d = threadIdx.x;
    int branch = bi >> 3, b = bi & 7;
    const bf16* xp = sp->xp[branch];
    const bf16* ga = sp->ga[branch];
    float s1 = 0.f, s2 = 0.f;
    int q0 = ch * 128;
    for (int q = q0; q < q0 + 128; q++) {
        long o = ((long)(b * kKP + q)) * kD + d;
        s1 += __bfloat162float(xp[o]);
        s2 += __bfloat162float(ga[o]);
    }
    sp->up[(bi * 6 + ch) * 512 + d] = s1;
    sp->up[(bi * 6 + ch) * 512 + 256 + d] = s2;
}
__global__ void featsum_red_k(Scratch* sp) {
    int bi = blockIdx.x, d = threadIdx.x;
    float s = 0.f;
    for (int ch = 0; ch < 6; ch++) s += sp->up[(bi * 6 + ch) * 512 + d];
    sp->u[bi * 512 + d] = s;
}
__global__ void cos_k(const float* __restrict__ u, float* __restrict__ out) {
    int b = blockIdx.x, t = threadIdx.x;
    float a = u[b * 512 + t];
    float c = u[(kB + b) * 512 + t];
    float dot = bsum(a * c);
    float na = bsum(a * a);
    float nc = bsum(c * c);
    if (t == 0)
        out[b] = dot / (fmaxf(sqrtf(na), 1e-8f) * fmaxf(sqrtf(nc), 1e-8f));
}

// ------------------------- host orchestration -------------------------
static void gemm(const bf16* A, int lda, long A2, long Ab, long Ah,
                 const bf16* Bm, int ldb, long B2, long Bb, long Bh,
                 bf16* C, int ldc, long C2, long Cb, long Ch,
                 const bf16* Add, int ldadd, const bf16* Add2, const float* gptr,
                 int M, int N, int K, int ZC, int ZB, int ZH, float alpha, int mode,
                 unsigned zmask = 0, long Aalt = 0, int Malt = 0,
                 long Valt = 0, int zsplit = 1 << 30) {
    int ZT = ZB * ZH;
    if (N % 128 == 0) {
        int sm = (2 * 128 * 40 + 2 * 128 * 40) * 2;
        dim3 g(M / 128, N / 128, ZC * ZT), blk(256);
        cudaFuncSetAttribute(hgemm_k<128>, cudaFuncAttributeMaxDynamicSharedMemorySize, sm);
        hgemm_k<128><<<g, blk, sm>>>(A, lda, A2, Ab, Ah, Bm, ldb, B2, Bb, Bh,
                                     C, ldc, C2, Cb, Ch, Add, ldadd, Add2, gptr,
                                     K, ZH, ZT, alpha, mode, zmask, Aalt, Malt, M,
                                     Valt, zsplit);
    } else {
        int sm = (2 * 128 * 40 + 2 * 64 * 40) * 2;
        dim3 g(M / 128, N / 64, ZC * ZT), blk(256);
        cudaFuncSetAttribute(hgemm_k<64>, cudaFuncAttributeMaxDynamicSharedMemorySize, sm);
        hgemm_k<64><<<g, blk, sm>>>(A, lda, A2, Ab, Ah, Bm, ldb, B2, Bb, Bh,
                                    C, ldc, C2, Cb, Ch, Add, ldadd, Add2, gptr,
                                    K, ZH, ZT, alpha, mode, zmask, Aalt, Malt, M,
                                    Valt, zsplit);
    }
}

extern "C" void kernel_launch(void* const* d_in, const int* in_sizes, int n_in,
                              void* d_out, int out_size) {
    Scratch* sp = nullptr;
    cudaGetSymbolAddress((void**)&sp, SC);

    const float* Wk    = (const float*)d_in[12];
    const float* Wq    = (const float*)d_in[13];
    const float* Wv    = (const float*)d_in[14];
    const float* Wo    = (const float*)d_in[15];
    const float* arel  = (const float*)d_in[16];
    const float* mrel  = (const float*)d_in[17];
    const float* prel  = (const float*)d_in[18];
    const float* skip  = (const float*)d_in[19];
    const float* poolW = (const float*)d_in[20];
    const float* poolA = (const float*)d_in[21];
    const float* poolB = (const float*)d_in[22];
    const float* tWq   = (const float*)d_in[23];
    const float* tWk   = (const float*)d_in[24];
    const float* tWv   = (const float*)d_in[25];
    const float* tWo   = (const float*)d_in[26];
    const float* lng   = (const float*)d_in[27];
    const float* lnb   = (const float*)d_in[28];

    const long T1 = (long)kNI * kD;

    pack_all_k<<<(int)((PWq + PT + PO + P2 + 255) / 256), 256>>>(
        Wq, tWq, tWk, tWv, Wo, tWo, sp);
    const int comb_smem = (256 * 65 + 4096) * 4;
    cudaFuncSetAttribute(pack_comb_k, cudaFuncAttributeMaxDynamicSharedMemorySize, comb_smem);
    pack_comb_k<<<128, 256, comb_smem>>>(Wk, Wv, arel, mrel, sp);
    assemble_x_k<<<(int)(2 * LXD / 4 + 255) / 256, 256>>>(
        (const float*)d_in[0], (const float*)d_in[1],
        (const float*)d_in[6], (const float*)d_in[7], sp);

    const int krel_smem = (128 * 264 + 4 * 64 * 264) * 2;
    cudaFuncSetAttribute(krel_k, cudaFuncAttributeMaxDynamicSharedMemorySize, krel_smem);

    bool csr_done = false;

    for (int l = 0; l < 2; l++) {
        for (int dir = 0; dir < 2; dir++) {
            int combo = l * 2 + dir;
            // Q only: z = (branch:2) x (type:2 via zb mask)
            gemm(&sp->x[0][0], kD, LXD, 0, 0,
                 sp->pWq + (long)(combo * 2) * 65536, 256, 0, 65536, 0,
                 &sp->qb[0][0], 256, LXD, (long)kNI * 256, 0,
                 nullptr, 0, nullptr, nullptr,
                 kNI, 256, kD, 2, 2, 1, 1.f, 0,
                 0x2u, T1, kND);
            // Krel+Vrel from combined weights (K=256)
            krel_k<<<dim3(96, 1, 16), 256, krel_smem>>>(sp, combo, dir);
            if (!csr_done) {
                for (int br = 0; br < 2; br++) {
                    const int* e = (const int*)d_in[br * 6 + 2];
                    const int *rc = e, *cc = e + kEC;
                    const int* e2 = (const int*)d_in[br * 6 + 3];
                    const int *ri = e2, *ci = e2 + kEI;
                    const int* e3 = (const int*)d_in[br * 6 + 4];
                    const int *ro = e3, *co = e3 + kEO;
                    const int* e4 = (const int*)d_in[br * 6 + 5];
                    const int *rk = e4, *ck = e4 + kEK;
                    csr_count_k<<<(BB11 + 255) / 256, 256>>>(sp, rc, cc, ri, ci, ro, co, rk, ck);
                    csr_scan_k<<<5, 1024>>>(sp, br);
                    csr_fill_k<<<(BB12 + 255) / 256, 256>>>(sp, br, rc, cc, ri, ci, ro, co, rk, ck);
                }
                csr_done = true;
            }
            hgt_agg_k<<<2 * kNT, 128>>>(sp, dir, prel + (long)(combo * 4) * kH);
            // Wo: z = (branch:2) x (type:2 via zb mask)
            const float* gp = skip + combo * 2;
            if (dir == 0)
                gemm(&sp->agg[0][0], kD, LXD, 0, 0,
                     sp->pWo + (long)(combo * 2) * 65536, 256, 0, 65536, 0,
                     &sp->yF[0][0], kD, LXD, T1, 0, &sp->x[0][0], kD, nullptr, gp,
                     kNI, kD, kD, 2, 2, 1, 1.f, 1,
                     0x2u, T1, kND);
            else
                gemm(&sp->agg[0][0], kD, LXD, 0, 0,
                     sp->pWo + (long)(combo * 2) * 65536, 256, 0, 65536, 0,
                     &sp->x[0][0], kD, LXD, T1, 0, &sp->x[0][0], kD, &sp->yF[0][0], gp,
                     kNI, kD, kD, 2, 2, 1, 1.f, 3,
                     0x2u, T1, kND);
        }
    }

    // pooling (both branches)
    hv_k<<<2 * kNT / 8, 256>>>(sp, poolW);
    gat_score_k<<<(2 * kNT + 255) / 256, 256>>>(sp, poolA, poolB);
    topk_sort_k<<<16, 1024>>>(sp);
    gather_k<<<dim3(kKP, 16), kD>>>(sp);

    // transformer attention (both branches)
    int Mp = kB * kKP;
    long pq = (long)kKP * 768;
    gemm(&sp->xp[0][0], kD, LPD, 0, 0, sp->pTw, 256, 0, 0, 0,
         &sp->qkvp[0][0], 768, 3 * LPD, 0, 0,
         nullptr, 0, nullptr, nullptr, Mp, 768, kD, 2, 1, 1, 1.f, 0);
    gemm(&sp->qkvp[0][0], 768, 3 * LPD, pq, kDH,
         &sp->qkvp[0][0] + 256, 768, 3 * LPD, pq, kDH,
         &sp->S[0][0], kKP, SLEN, (long)kH * kKP * kKP, (long)kKP * kKP,
         nullptr, 0, nullptr, nullptr,
         kKP, kKP, kDH, 2, kB, kH, 0.125f, 0);
    softmax_k<<<2 * kB * kH * kKP, 256>>>(&sp->S[0][0]);
    vtrans_k<<<(int)((2L * kB * kH * 64 * kKP + 255) / 256), 256>>>(sp);
    gemm(&sp->S[0][0], kKP, SLEN, (long)kH * kKP * kKP, (long)kKP * kKP,
         &sp->vT[0][0], kKP, (long)kB * kH * 64 * kKP, (long)kH * 64 * kKP, (long)64 * kKP,
         &sp->oh[0][0], kD, LPD, (long)kKP * kD, kDH,
         nullptr, 0, nullptr, nullptr,
         kKP, kDH, kKP, 2, kB, kH, 1.f, 0);
    gemm(&sp->oh[0][0], kD, LPD, 0, 0, sp->pTwo, 256, 0, 0, 0,
         &sp->yb[0][0], kD, LPD, 0, 0,
         &sp->xp[0][0], kD, nullptr, nullptr, Mp, kD, kD, 2, 1, 1, 1.f, 2);
    ln_k<<<2 * Mp, kD>>>(&sp->yb[0][0], lng, lnb, &sp->ga[0][0]);
    featsum_part_k<<<dim3(16, 6), 256>>>(sp);
    featsum_red_k<<<16, 512>>>(sp);
    cos_k<<<kB, 512>>>(sp->u, (float*)d_out);
}

// round 16
// speedup vs baseline: 1.1176x; 1.1176x over previous
#include <cuda_runtime.h>
#include <cuda_bf16.h>
#include <math.h>
#include <stdint.h>

// ------------------------- problem constants -------------------------
constexpr int kNI = 8192, kND = 4096, kNT = 12288, kD = 256, kH = 4, kDH = 64;
constexpr int kB = 8, kKP = 768;
constexpr int kEC = 65536, kEI = 32768, kEO = 32768, kEK = 8192;
constexpr long LXD = (long)kNT * kD;
constexpr long LPD = (long)kB * kKP * kD;
constexpr long KRVB = 8L * kNI * 256;          // bf16 elems per branch (K rels 0-3, V 4-7)
constexpr long SLEN = (long)kB * kH * kKP * kKP;

constexpr int O0 = 0;
constexpr int O1 = kNI;
constexpr int O2 = kNI + kND;
constexpr int O3 = 2 * kNI + kND;
constexpr int O4 = 2 * kNI + 2 * kND;
constexpr int CNT_TOT = O4 + kNT;

constexpr int BB0 = kEC;
constexpr int BB1 = BB0 + kEI;
constexpr int BB2 = BB1 + kEK;
constexpr int BB3 = BB2 + kEO;
constexpr int BB4 = BB3 + kEC;
constexpr int BB5 = BB4 + kEO;
constexpr int BB6 = BB5 + kEK;
constexpr int BB7 = BB6 + kEI;
constexpr int BB8 = BB7 + kEC;
constexpr int BB9 = BB8 + kEI;
constexpr int BB10 = BB9 + kEO;
constexpr int BB11 = BB10 + kEK;
constexpr int BB12 = BB11 + kNT;

typedef __nv_bfloat16 bf16;
typedef __nv_bfloat162 bf162;

// ------------------------- scratch -------------------------
struct Scratch {
    bf16 x[2][LXD], yF[2][LXD], agg[2][LXD];
    bf16 kqv[2][3 * LXD];                     // [branch][node][768] K|Q|V
    bf16 krv[2][KRVB];                        // [relslot 0-7][node][256]
    bf16 S[2][SLEN];
    bf16 xp[2][LPD], qkvp[2][3 * LPD], oh[2][LPD], yb[2][LPD], ga[2][LPD];
    bf16 vT[2][(long)kB * kH * 64 * kKP];     // V transposed [b][h][dh][key]
    bf16 pW[8L * 768 * 256];                  // [combo*2+t][n][k]
    bf16 pTw[768L * 256];
    bf16 pRel[4L * 8 * 4 * 64 * 64];          // [combo][relslot][h][n][k]
    bf16 pWo[8L * 256 * 256];
    bf16 pTwo[256L * 256];
    float hv[2 * kNT], sc[2 * kNT];
    float sv[2 * kB * kKP];
    int   si[2 * kB * kKP];
    float u[2 * kB * 512];
    float up[2 * kB * 6 * 512];
    int rpf0[2][kNI + 1], rpf1[2][kND + 1], rpr0[2][kNI + 1], rpr1[2][kND + 1], rph[2][kNT + 1];
    int ef0[2][kEC + kEI + kEK], ef1[2][kEO], er0[2][kEC + kEO + kEK], er1[2][kEI];
    int eh[2][kEC + kEI + kEO + kEK + kNT];
    int cnt[CNT_TOT], cur[CNT_TOT];
};
__device__ Scratch SC;

// ------------------------- reductions -------------------------
__device__ __forceinline__ float wsum(float v) {
#pragma unroll
    for (int o = 16; o; o >>= 1) v += __shfl_xor_sync(0xffffffffu, v, o);
    return v;
}
__device__ __forceinline__ float bsum(float v) {
    __shared__ float sh[32];
    int lane = threadIdx.x & 31, w = threadIdx.x >> 5;
    v = wsum(v);
    if (!lane) sh[w] = v;
    __syncthreads();
    int nw = blockDim.x >> 5;
    float s = (threadIdx.x < nw) ? sh[threadIdx.x] : 0.f;
    if (w == 0) s = wsum(s);
    if (threadIdx.x == 0) sh[0] = s;
    __syncthreads();
    float r = sh[0];
    __syncthreads();
    return r;
}
__device__ __forceinline__ float bmax(float v) {
    __shared__ float sh[32];
    int lane = threadIdx.x & 31, w = threadIdx.x >> 5;
#pragma unroll
    for (int o = 16; o; o >>= 1) v = fmaxf(v, __shfl_xor_sync(0xffffffffu, v, o));
    if (!lane) sh[w] = v;
    __syncthreads();
    int nw = blockDim.x >> 5;
    float s = (threadIdx.x < nw) ? sh[threadIdx.x] : -INFINITY;
    if (w == 0)
#pragma unroll
        for (int o = 16; o; o >>= 1) s = fmaxf(s, __shfl_xor_sync(0xffffffffu, s, o));
    if (threadIdx.x == 0) sh[0] = s;
    __syncthreads();
    float r = sh[0];
    __syncthreads();
    return r;
}

// ------------------------- bf16 mma helpers -------------------------
__device__ __forceinline__ void mma_bf16(float* c, const uint32_t* a,
                                         uint32_t b0, uint32_t b1) {
    asm volatile(
        "mma.sync.aligned.m16n8k16.row.col.f32.bf16.bf16.f32 "
        "{%0,%1,%2,%3}, {%4,%5,%6,%7}, {%8,%9}, {%0,%1,%2,%3};"
        : "+f"(c[0]), "+f"(c[1]), "+f"(c[2]), "+f"(c[3])
        : "r"(a[0]), "r"(a[1]), "r"(a[2]), "r"(a[3]), "r"(b0), "r"(b1));
}
__device__ __forceinline__ void cpa16(void* dst, const void* src) {
    unsigned d = (unsigned)__cvta_generic_to_shared(dst);
    asm volatile("cp.async.cg.shared.global [%0], [%1], 16;\n" :: "r"(d), "l"(src));
}
#define CP_COMMIT() asm volatile("cp.async.commit_group;\n" ::: "memory")
#define CP_WAIT1()  asm volatile("cp.async.wait_group 1;\n" ::: "memory")
#define CP_WAIT0()  asm volatile("cp.async.wait_group 0;\n" ::: "memory")

// ------------------------- generic bf16 GEMM (cp.async pipelined) --------
template <int BN>
__global__ void __launch_bounds__(256, 2) hgemm_k(
    const bf16* __restrict__ A, int lda, long A2, long Ab, long Ah,
    const bf16* __restrict__ Bm, int ldb, long B2, long Bb, long Bh,
    bf16* __restrict__ C, int ldc, long C2, long Cb, long Ch,
    const bf16* __restrict__ Add, int ldadd, const bf16* __restrict__ Add2,
    const float* __restrict__ gptr,
    int Kdim, int ZH, int ZT, float alpha, int mode,
    unsigned zmask, long Aalt, int Malt, int Mdef, long Valt, int zsplit)
{
    constexpr int BM = 128, BK = 32;
    constexpr int STR = 40;
    constexpr int TN = (BN == 128) ? 8 : 4;
    extern __shared__ bf16 smh_[];
    bf16* As = smh_;
    bf16* Bs = smh_ + 2 * BM * STR;

    int z = blockIdx.z;
    int z2 = z / ZT, rz = z - z2 * ZT;
    int zb = rz / ZH, zh = rz - zb * ZH;
    int msk = (zmask >> zb) & 1;
    int Mz = msk ? Malt : Mdef;
    int m0 = blockIdx.x * BM;
    if (m0 >= Mz) return;
    const bf16* Ax = A + z2 * A2 + zb * Ab + zh * Ah + (msk ? Aalt : 0)
                       + (zb >= zsplit ? Valt : 0);
    const bf16* Bx = Bm + z2 * B2 + zb * Bb + zh * Bh;
    long coff = z2 * C2 + zb * Cb + zh * Ch;
    C += coff;
    if (Add)  Add  += coff;
    if (Add2) Add2 += coff;
    int n0 = blockIdx.y * BN;
    int tid = threadIdx.x, lane = tid & 31, warp = tid >> 5;
    int wm = warp >> 1, wn = warp & 1;
    int g = lane >> 2, tg = lane & 3;

    float acc[2][TN][4];
#pragma unroll
    for (int i = 0; i < 2; i++)
#pragma unroll
        for (int j = 0; j < TN; j++)
#pragma unroll
            for (int q = 0; q < 4; q++) acc[i][j][q] = 0.f;

    int nt = Kdim / BK;

#define ISSUE(K0, Sg) do {                                                     \
        bf16* Ad = As + (Sg) * BM * STR;                                       \
        _Pragma("unroll")                                                      \
        for (int q = 0; q < 2; q++) {                                          \
            int f = tid + q * 256, row = f >> 2, kc = (f & 3) * 8;             \
            cpa16(Ad + row * STR + kc,                                         \
                  Ax + (long)(m0 + row) * lda + (K0) + kc);                    \
        }                                                                      \
        bf16* Bd = Bs + (Sg) * BN * STR;                                       \
        _Pragma("unroll")                                                      \
        for (int q = 0; q < BN / 64; q++) {                                    \
            int f = tid + q * 256, row = f >> 2, kc = (f & 3) * 8;             \
            cpa16(Bd + row * STR + kc,                                         \
                  Bx + (long)(n0 + row) * ldb + (K0) + kc);                    \
        }                                                                      \
    } while (0)

    ISSUE(0, 0);
    CP_COMMIT();

    for (int t = 0; t < nt; t++) {
        if (t + 1 < nt) {
            ISSUE((t + 1) * BK, (t + 1) & 1);
            CP_COMMIT();
            CP_WAIT1();
        } else {
            CP_WAIT0();
        }
        __syncthreads();
        const bf16* Ap = As + (size_t)(t & 1) * BM * STR;
        const bf16* Bp = Bs + (size_t)(t & 1) * BN * STR;
#pragma unroll
        for (int k16 = 0; k16 < 2; k16++) {
            int kb = k16 * 16;
            uint32_t a[2][4];
#pragma unroll
            for (int tm = 0; tm < 2; tm++) {
                int mr = wm * 32 + tm * 16;
                a[tm][0] = *(const uint32_t*)(Ap + (mr + g) * STR + kb + 2 * tg);
                a[tm][1] = *(const uint32_t*)(Ap + (mr + 8 + g) * STR + kb + 2 * tg);
                a[tm][2] = *(const uint32_t*)(Ap + (mr + g) * STR + kb + 2 * tg + 8);
                a[tm][3] = *(const uint32_t*)(Ap + (mr + 8 + g) * STR + kb + 2 * tg + 8);
            }
#pragma unroll
            for (int tn = 0; tn < TN; tn++) {
                int nc = wn * (TN * 8) + tn * 8 + g;
                uint32_t b0 = *(const uint32_t*)(Bp + nc * STR + kb + 2 * tg);
                uint32_t b1 = *(const uint32_t*)(Bp + nc * STR + kb + 2 * tg + 8);
#pragma unroll
                for (int tm = 0; tm < 2; tm++)
                    mma_bf16(acc[tm][tn], a[tm], b0, b1);
            }
        }
        __syncthreads();
    }
#undef ISSUE

    float gg = 1.f;
    if (mode == 1 || mode == 3) gg = 1.f / (1.f + expf(-gptr[zb]));
#pragma unroll
    for (int tm = 0; tm < 2; tm++) {
        long row0 = m0 + wm * 32 + tm * 16 + g;
#pragma unroll
        for (int tn = 0; tn < TN; tn++) {
            long col = n0 + wn * (TN * 8) + tn * 8 + tg * 2;
#pragma unroll
            for (int half = 0; half < 2; half++) {
                long r = row0 + half * 8;
                float vx = alpha * acc[tm][tn][half * 2 + 0];
                float vy = alpha * acc[tm][tn][half * 2 + 1];
                if (mode == 1) {
                    float2 ad = __bfloat1622float2(*(const bf162*)(Add + r * ldadd + col));
                    vx = gg * vx + (1.f - gg) * ad.x;
                    vy = gg * vy + (1.f - gg) * ad.y;
                } else if (mode == 2) {
                    float2 ad = __bfloat1622float2(*(const bf162*)(Add + r * ldadd + col));
                    vx += ad.x; vy += ad.y;
                } else if (mode == 3) {
                    float2 ad = __bfloat1622float2(*(const bf162*)(Add + r * ldadd + col));
                    float2 a2 = __bfloat1622float2(*(const bf162*)(Add2 + r * ldadd + col));
                    vx = 0.5f * (gg * vx + (1.f - gg) * ad.x) + 0.5f * a2.x;
                    vy = 0.5f * (gg * vy + (1.f - gg) * ad.y) + 0.5f * a2.y;
                    vx = vx > 0.f ? vx : 0.f;
                    vy = vy > 0.f ? vy : 0.f;
                }
                *(bf162*)(C + r * ldc + col) = __floats2bfloat162_rn(vx, vy);
            }
        }
    }
}

// ---------------- specialized Krel/Vrel kernel: A-tile reuse over 4 relations ----
__global__ void __launch_bounds__(256) krel_k(Scratch* sp, int combo, int dir) {
    constexpr int STR = 72;
    extern __shared__ bf16 smk_[];
    bf16* As = smk_;                 // [128][STR]
    bf16* Bs = smk_ + 128 * STR;     // [4][64][STR]
    int z = blockIdx.z;
    int branch = z >> 3, rem = z & 7;
    int kv = rem >> 2, h = rem & 3;
    int m0 = blockIdx.x * 128;
    int tid = threadIdx.x;
    const bf16* Aptr = sp->kqv[branch] + (long)m0 * 768 + kv * 512 + h * 64;
#pragma unroll
    for (int q = 0; q < 4; q++) {
        int f = tid + q * 256;
        int row = f >> 3, kc = (f & 7) * 8;
        cpa16(As + row * STR + kc, Aptr + (long)row * 768 + kc);
    }
#pragma unroll
    for (int r = 0; r < 4; r++) {
        const bf16* Bp = sp->pRel + (long)combo * 131072
                         + (((long)(kv * 4 + r) * 4 + h) * 4096);
        bf16* Bd = Bs + r * 64 * STR;
#pragma unroll
        for (int q = 0; q < 2; q++) {
            int f = tid + q * 256;
            int row = f >> 3, kc = (f & 7) * 8;
            cpa16(Bd + row * STR + kc, Bp + (long)row * 64 + kc);
        }
    }
    CP_COMMIT();
    CP_WAIT0();
    __syncthreads();
    int lane = tid & 31, warp = tid >> 5;
    int wm = warp >> 1, wn = warp & 1;
    int g = lane >> 2, tg = lane & 3;
    uint32_t a[2][4][4];
#pragma unroll
    for (int k16 = 0; k16 < 4; k16++) {
        int kb = k16 * 16;
#pragma unroll
        for (int tm = 0; tm < 2; tm++) {
            int mr = wm * 32 + tm * 16;
            a[tm][k16][0] = *(const uint32_t*)(As + (mr + g) * STR + kb + 2 * tg);
            a[tm][k16][1] = *(const uint32_t*)(As + (mr + 8 + g) * STR + kb + 2 * tg);
            a[tm][k16][2] = *(const uint32_t*)(As + (mr + g) * STR + kb + 2 * tg + 8);
            a[tm][k16][3] = *(const uint32_t*)(As + (mr + 8 + g) * STR + kb + 2 * tg + 8);
        }
    }
#pragma unroll
    for (int r = 0; r < 4; r++) {
        int srcData = (dir == 0) ? (r == 1) : (r == 2);
        if (srcData ? (m0 < 8192) : (m0 >= 8192)) continue;
        const bf16* Bp = Bs + r * 64 * STR;
        float acc[2][4][4];
#pragma unroll
        for (int i = 0; i < 2; i++)
#pragma unroll
            for (int j = 0; j < 4; j++)
#pragma unroll
                for (int q = 0; q < 4; q++) acc[i][j][q] = 0.f;
#pragma unroll
        for (int k16 = 0; k16 < 4; k16++) {
            int kb = k16 * 16;
#pragma unroll
            for (int tn = 0; tn < 4; tn++) {
                int nc = wn * 32 + tn * 8 + g;
                uint32_t b0 = *(const uint32_t*)(Bp + nc * STR + kb + 2 * tg);
                uint32_t b1 = *(const uint32_t*)(Bp + nc * STR + kb + 2 * tg + 8);
                mma_bf16(acc[0][tn], a[0][k16], b0, b1);
                mma_bf16(acc[1][tn], a[1][k16], b0, b1);
            }
        }
        int slot = kv * 4 + r;
        long crow0 = m0 - (srcData ? 8192 : 0);
        bf16* C = sp->krv[branch] + ((long)slot * kNI + crow0) * 256 + h * 64;
#pragma unroll
        for (int tm = 0; tm < 2; tm++) {
            long row0 = wm * 32 + tm * 16 + g;
#pragma unroll
            for (int tn = 0; tn < 4; tn++) {
                long col = wn * 32 + tn * 8 + tg * 2;
#pragma unroll
                for (int half = 0; half < 2; half++) {
                    long rr = row0 + half * 8;
                    *(bf162*)(C + rr * 256 + col) =
                        __floats2bfloat162_rn(acc[tm][tn][half * 2 + 0],
                                              acc[tm][tn][half * 2 + 1]);
                }
            }
        }
    }
}

// ------------------------- fused weight packing (all -> bf16, [n][k]) -------
constexpr long PW = 8L * 768 * 256;
constexpr long PT = 768L * 256;
constexpr long PR = 4L * 8 * 4 * 4096;
constexpr long PO = 8L * 256 * 256;
constexpr long P2 = 256L * 256;
__global__ void pack_all_k(const float* __restrict__ Wk, const float* __restrict__ Wq,
                           const float* __restrict__ Wv, const float* __restrict__ tWq,
                           const float* __restrict__ tWk, const float* __restrict__ tWv,
                           const float* __restrict__ arel, const float* __restrict__ mrel,
                           const float* __restrict__ Wo, const float* __restrict__ tWo,
                           Scratch* sp) {
    long i = (long)blockIdx.x * 256 + threadIdx.x;
    if (i < PW) {
        long c = i / (768 * 256), r = i % (768 * 256);
        int n = (int)(r / 256), k = (int)(r % 256);
        int sel = n >> 8, nn = n & 255;
        const float* W = (sel == 0) ? Wk : (sel == 1) ? Wq : Wv;
        sp->pW[i] = __float2bfloat16(W[c * 65536 + (long)k * 256 + nn]);
    } else if (i < PW + PT) {
        long j = i - PW;
        int n = (int)(j / 256), k = (int)(j % 256);
        int sel = n >> 8, nn = n & 255;
        const float* W = (sel == 0) ? tWq : (sel == 1) ? tWk : tWv;
        sp->pTw[j] = __float2bfloat16(W[(long)k * 256 + nn]);
    } else if (i < PW + PT + PR) {
        long j = i - PW - PT;
        int k  = (int)(j & 63);
        int n  = (int)((j >> 6) & 63);
        int hh = (int)((j >> 12) & 3);
        int zr = (int)((j >> 14) & 7);
        int c  = (int)(j >> 17);
        const float* src = (zr < 4) ? arel : mrel;
        int rr = zr & 3;
        sp->pRel[j] = __float2bfloat16(src[(((long)(c * 4 + rr) * 4 + hh) << 12) + k * 64 + n]);
    } else if (i < PW + PT + PR + PO) {
        long j = i - PW - PT - PR;
        long c = j / 65536, r = j % 65536;
        int n = (int)(r / 256), k = (int)(r % 256);
        sp->pWo[j] = __float2bfloat16(Wo[c * 65536 + (long)k * 256 + n]);
    } else if (i < PW + PT + PR + PO + P2) {
        long j = i - PW - PT - PR - PO;
        int n = (int)(j / 256), k = (int)(j % 256);
        sp->pTwo[j] = __float2bfloat16(tWo[(long)k * 256 + n]);
    }
}

// ------------------------- elementwise -------------------------
__global__ void assemble_x_k(const float* __restrict__ xi0, const float* __restrict__ xd0,
                             const float* __restrict__ xi1, const float* __restrict__ xd1,
                             Scratch* sp) {
    long i = ((long)blockIdx.x * blockDim.x + threadIdx.x) * 4;
    if (i < 2 * LXD) {
        const long T1 = (long)kNI * kD;
        int br = i >= LXD;
        long loc = i - (long)br * LXD;
        const float* xi = br ? xi1 : xi0;
        const float* xd = br ? xd1 : xd0;
        float4 v = (loc < T1) ? *(const float4*)(xi + loc) : *(const float4*)(xd + (loc - T1));
        bf162 h0 = __floats2bfloat162_rn(v.x, v.y);
        bf162 h1 = __floats2bfloat162_rn(v.z, v.w);
        *(bf162*)(&sp->x[0][0] + i) = h0;
        *(bf162*)(&sp->x[0][0] + i + 2) = h1;
    }
}
__global__ void vtrans_k(Scratch* sp) {
    long i = (long)blockIdx.x * blockDim.x + threadIdx.x;
    if (i >= 2L * kB * kH * 64 * kKP) return;
    int key = (int)(i % kKP);
    long r = i / kKP;
    int dh = (int)(r & 63);
    long r2 = r >> 6;
    int h = (int)(r2 & 3);
    long r3 = r2 >> 2;
    int b = (int)(r3 & 7);
    int br = (int)(r3 >> 3);
    sp->vT[br][(((long)b * 4 + h) * 64 + dh) * kKP + key] =
        sp->qkvp[br][((long)b * kKP + key) * 768 + 512 + h * 64 + dh];
}

// ------------------------- fused CSR construction -------------------------
struct Slot { int idx; int ent; int arr; };
__device__ __forceinline__ Slot decode_slot(
    int i, const int* rc, const int* cc, const int* ri, const int* ci,
    const int* ro, const int* co, const int* rk, const int* ck)
{
    Slot s;
    if (i < BB0)       { s.idx = O0 + cc[i];            s.ent = (0 << 16) | rc[i];            s.arr = 0; }
    else if (i < BB1)  { int j = i - BB0;  s.idx = O0 + ci[j]; s.ent = (1 << 16) | ri[j];     s.arr = 0; }
    else if (i < BB2)  { int j = i - BB1;  s.idx = O0 + ck[j]; s.ent = (3 << 16) | rk[j];     s.arr = 0; }
    else if (i < BB3)  { int j = i - BB2;  s.idx = O1 + co[j]; s.ent = (2 << 16) | ro[j];     s.arr = 1; }
    else if (i < BB4)  { int j = i - BB3;  s.idx = O2 + rc[j]; s.ent = (0 << 16) | cc[j];     s.arr = 2; }
    else if (i < BB5)  { int j = i - BB4;  s.idx = O2 + ro[j]; s.ent = (2 << 16) | co[j];     s.arr = 2; }
    else if (i < BB6)  { int j = i - BB5;  s.idx = O2 + rk[j]; s.ent = (3 << 16) | ck[j];     s.arr = 2; }
    else if (i < BB7)  { int j = i - BB6;  s.idx = O3 + ri[j]; s.ent = (1 << 16) | ci[j];     s.arr = 3; }
    else if (i < BB8)  { int j = i - BB7;  s.idx = O4 + cc[j]; s.ent = rc[j];                 s.arr = 4; }
    else if (i < BB9)  { int j = i - BB8;  s.idx = O4 + ci[j]; s.ent = ri[j] + kNI;           s.arr = 4; }
    else if (i < BB10) { int j = i - BB9;  s.idx = O4 + co[j] + kNI; s.ent = ro[j];           s.arr = 4; }
    else               { int j = i - BB10; s.idx = O4 + ck[j]; s.ent = rk[j];                 s.arr = 4; }
    return s;
}

__global__ void csr_count_k(Scratch* sp, const int* rc, const int* cc,
                            const int* ri, const int* ci, const int* ro, const int* co,
                            const int* rk, const int* ck) {
    int i = blockIdx.x * blockDim.x + threadIdx.x;
    if (i < BB11) {
        Slot s = decode_slot(i, rc, cc, ri, ci, ro, co, rk, ck);
        atomicAdd(&sp->cnt[s.idx], 1);
    }
}
__global__ void csr_scan_k(Scratch* sp, int br) {
    __shared__ int sh[1024];
    int region = blockIdx.x, t = threadIdx.x;
    int off, n, extra = 0;
    int* rp;
    switch (region) {
        case 0: off = O0; n = kNI; rp = sp->rpf0[br]; break;
        case 1: off = O1; n = kND; rp = sp->rpf1[br]; break;
        case 2: off = O2; n = kNI; rp = sp->rpr0[br]; break;
        case 3: off = O3; n = kND; rp = sp->rpr1[br]; break;
        default: off = O4; n = kNT; rp = sp->rph[br]; extra = 1; break;
    }
    int c = (n + 1023) >> 10;
    int beg = t * c, end = min(beg + c, n);
    int s = 0;
    for (int i = beg; i < end; i++) s += sp->cnt[off + i] + extra;
    sh[t] = s;
    __syncthreads();
    for (int o = 1; o < 1024; o <<= 1) {
        int v = (t >= o) ? sh[t - o] : 0;
        __syncthreads();
        sh[t] += v;
        __syncthreads();
    }
    int run = t ? sh[t - 1] : 0;
    for (int i = beg; i < end; i++) {
        int cv = sp->cnt[off + i];
        sp->cnt[off + i] = 0;
        rp[i] = run;
        sp->cur[off + i] = run;
        run += cv + extra;
    }
    if (t == 1023) rp[n] = sh[1023];
}
__global__ void csr_fill_k(Scratch* sp, int br, const int* rc, const int* cc,
                           const int* ri, const int* ci, const int* ro, const int* co,
                           const int* rk, const int* ck) {
    int i = blockIdx.x * blockDim.x + threadIdx.x;
    if (i >= BB12) return;
    if (i < BB11) {
        Slot s = decode_slot(i, rc, cc, ri, ci, ro, co, rk, ck);
        int pos = atomicAdd(&sp->cur[s.idx], 1);
        switch (s.arr) {
            case 0: sp->ef0[br][pos] = s.ent; break;
            case 1: sp->ef1[br][pos] = s.ent; break;
            case 2: sp->er0[br][pos] = s.ent; break;
            case 3: sp->er1[br][pos] = s.ent; break;
            default: sp->eh[br][pos] = s.ent; break;
        }
    } else {
        int node = i - BB11;
        int pos = atomicAdd(&sp->cur[O4 + node], 1);
        sp->eh[br][pos] = node;
    }
}

// ------------------- HGT softmax aggregation (4-edge ILP, kqv Q layout) ------
__global__ void hgt_agg_k(Scratch* sp, int dir, const float* __restrict__ prel) {
    int nb = blockIdx.x;
    int branch = nb >= kNT;
    int node = nb - branch * kNT;
    const int *rp, *ent; int idx;
    if (dir == 0) {
        if (node < kNI) { rp = sp->rpf0[branch]; ent = sp->ef0[branch]; idx = node; }
        else            { rp = sp->rpf1[branch]; ent = sp->ef1[branch]; idx = node - kNI; }
    } else {
        if (node < kNI) { rp = sp->rpr0[branch]; ent = sp->er0[branch]; idx = node; }
        else            { rp = sp->rpr1[branch]; ent = sp->er1[branch]; idx = node - kNI; }
    }
    int h = threadIdx.x >> 5, lane = threadIdx.x & 31;
    long hoff = h * 64 + 2 * lane;
    float2 qq = __bfloat1622float2(
        *(const bf162*)(sp->kqv[branch] + (long)node * 768 + 256 + hoff));
    float q0 = qq.x, q1 = qq.y;
    const bf16* krv = sp->krv[branch];
    float pr0 = prel[0 * kH + h], pr1 = prel[1 * kH + h];
    float pr2 = prel[2 * kH + h], pr3 = prel[3 * kH + h];
    int s = rp[idx], eend = rp[idx + 1];
    float m = -INFINITY, den = 0.f, a0 = 0.f, a1 = 0.f;
    int e = s;
    for (; e + 3 < eend; e += 4) {
        int rr[4], ss[4];
#pragma unroll
        for (int u = 0; u < 4; u++) {
            int pk = ent[e + u];
            rr[u] = pk >> 16;
            ss[u] = pk & 0xffff;
        }
        float2 kk[4], vv[4];
#pragma unroll
        for (int u = 0; u < 4; u++) {
            kk[u] = __bfloat1622float2(
                *(const bf162*)(krv + ((long)rr[u] * kNI + ss[u]) * 256 + hoff));
            vv[u] = __bfloat1622float2(
                *(const bf162*)(krv + ((long)(rr[u] + 4) * kNI + ss[u]) * 256 + hoff));
        }
        float d[4];
#pragma unroll
        for (int u = 0; u < 4; u++) d[u] = q0 * kk[u].x + q1 * kk[u].y;
#pragma unroll
        for (int o = 16; o; o >>= 1) {
#pragma unroll
            for (int u = 0; u < 4; u++)
                d[u] += __shfl_xor_sync(0xffffffffu, d[u], o);
        }
        float sc4[4];
#pragma unroll
        for (int u = 0; u < 4; u++) {
            int r = rr[u];
            float pr = (r == 0) ? pr0 : (r == 1) ? pr1 : (r == 2) ? pr2 : pr3;
            sc4[u] = d[u] * pr * 0.125f;
        }
        float mn = fmaxf(fmaxf(m, fmaxf(sc4[0], sc4[1])), fmaxf(sc4[2], sc4[3]));
        float cc = expf(m - mn);
        float w0 = expf(sc4[0] - mn), w1 = expf(sc4[1] - mn);
        float w2 = expf(sc4[2] - mn), w3 = expf(sc4[3] - mn);
        den = den * cc + w0 + w1 + w2 + w3;
        a0 = a0 * cc + w0 * vv[0].x + w1 * vv[1].x + w2 * vv[2].x + w3 * vv[3].x;
        a1 = a1 * cc + w0 * vv[0].y + w1 * vv[1].y + w2 * vv[2].y + w3 * vv[3].y;
        m = mn;
    }
    for (; e < eend; e++) {
        int pk = ent[e];
        int r = pk >> 16, src = pk & 0xffff;
        float2 kk = __bfloat1622float2(
            *(const bf162*)(krv + ((long)r * kNI + src) * 256 + hoff));
        float2 vv = __bfloat1622float2(
            *(const bf162*)(krv + ((long)(r + 4) * kNI + src) * 256 + hoff));
        float d0 = q0 * kk.x + q1 * kk.y;
        d0 = wsum(d0);
        float pr = (r == 0) ? pr0 : (r == 1) ? pr1 : (r == 2) ? pr2 : pr3;
        float sc2 = d0 * pr * 0.125f;
        float mn = fmaxf(m, sc2);
        float cc = expf(m - mn), w = expf(sc2 - mn);
        den = den * cc + w;
        a0 = a0 * cc + w * vv.x;
        a1 = a1 * cc + w * vv.y;
        m = mn;
    }
    float inv = 1.f / (den + 1e-16f);
    float r0 = a0 * inv, r1 = a1 * inv;
    float g0 = 0.5f * r0 * (1.f + erff(r0 * 0.7071067811865475f));
    float g1 = 0.5f * r1 * (1.f + erff(r1 * 0.7071067811865475f));
    *(bf162*)(sp->agg[branch] + (long)node * kD + hoff) = __floats2bfloat162_rn(g0, g1);
}

// ------------------------- pooling -------------------------
__global__ void hv_k(Scratch* sp, const float* __restrict__ pw) {
    int nb = blockIdx.x * 8 + (threadIdx.x >> 5);
    int lane = threadIdx.x & 31;
    if (nb >= 2 * kNT) return;
    const bf16* x = &sp->x[0][0];
    float s = 0.f;
    for (int d = lane * 2; d < kD; d += 64) {
        float2 v = __bfloat1622float2(*(const bf162*)(x + (long)nb * kD + d));
        s += v.x * pw[d] + v.y * pw[d + 1];
    }
    s = wsum(s);
    if (!lane) sp->hv[nb] = s;
}
__global__ void gat_score_k(Scratch* sp, const float* __restrict__ att,
                            const float* __restrict__ bias) {
    int i = blockIdx.x * blockDim.x + threadIdx.x;
    if (i >= 2 * kNT) return;
    int branch = i / kNT, ii = i - branch * kNT;
    const int* rp = sp->rph[branch];
    const int* ent = sp->eh[branch];
    float A0 = att[0], A1 = att[1];
    float hi = sp->hv[i];
    int s = rp[ii], e1 = rp[ii + 1];
    float m = -INFINITY, den = 0.f, acc = 0.f;
    int hb = branch * kNT;
    for (int e = s; e < e1; e++) {
        int src = ent[e] & 0xffff;
        float hs = sp->hv[hb + src];
        float ee = A0 * hs + A1 * hi;
        ee = ee >= 0.f ? ee : 0.2f * ee;
        float mn = fmaxf(m, ee);
        float c = expf(m - mn), w = expf(ee - mn);
        den = den * c + w;
        acc = acc * c + w * hs;
        m = mn;
    }
    sp->sc[i] = acc / (den + 1e-16f) + bias[0];
}

__global__ void topk_sort_k(Scratch* sp) {
    int bi = blockIdx.x;
    int branch = bi >> 3, b = bi & 7;
    int t = threadIdx.x;
    const float* sc = sp->sc + branch * kNT;
    __shared__ float v[2048];
    __shared__ int ix[2048];
    for (int p = t; p < 2048; p += 1024) {
        float val = -INFINITY;
        if (p < 1536) {
            int node = p < 1024 ? b * 1024 + p : kNI + b * 512 + (p - 1024);
            val = sc[node];
        }
        v[p] = val;
        ix[p] = p;
    }
    __syncthreads();
    for (int k = 2; k <= 2048; k <<= 1)
        for (int j = k >> 1; j > 0; j >>= 1) {
#pragma unroll
            for (int pass = 0; pass < 2; pass++) {
                int i = t + pass * 1024;
                int l = i ^ j;
                if (l > i) {
                    bool up = ((i & k) == 0);
                    float vi = v[i], vl = v[l];
                    int ii = ix[i], il = ix[l];
                    bool before = (vi > vl) || (vi == vl && ii < il);
                    if (up != before) {
                        v[i] = vl; v[l] = vi;
                        ix[i] = il; ix[l] = ii;
                    }
                }
            }
            __syncthreads();
        }
    if (t < kKP) {
        sp->sv[bi * kKP + t] = v[t];
        sp->si[bi * kKP + t] = ix[t];
    }
}
__global__ void gather_k(Scratch* sp) {
    int q = blockIdx.x, bi = blockIdx.y, d = threadIdx.x;
    int branch = bi >> 3, b = bi & 7;
    int j = sp->si[bi * kKP + q];
    float tv = tanhf(sp->sv[bi * kKP + q]);
    int node = j < 1024 ? b * 1024 + j : kNI + b * 512 + (j - 1024);
    float vv = __bfloat162float(sp->x[branch][(long)node * kD + d]) * tv;
    sp->xp[branch][((long)(b * kKP + q)) * kD + d] = __float2bfloat16(vv);
}

// ------------------------- transformer pieces -------------------------
__global__ void softmax_k(bf16* __restrict__ S) {
    long row = blockIdx.x;
    bf16* p = S + row * kKP;
    int t = threadIdx.x;
    float v0 = __bfloat162float(p[t]);
    float v1 = __bfloat162float(p[t + 256]);
    float v2 = __bfloat162float(p[t + 512]);
    float m = bmax(fmaxf(v0, fmaxf(v1, v2)));
    v0 = expf(v0 - m); v1 = expf(v1 - m); v2 = expf(v2 - m);
    float s = bsum(v0 + v1 + v2);
    float inv = 1.f / s;
    p[t] = __float2bfloat16(v0 * inv);
    p[t + 256] = __float2bfloat16(v1 * inv);
    p[t + 512] = __float2bfloat16(v2 * inv);
}
__global__ void ln_k(const bf16* __restrict__ y, const float* __restrict__ g,
                     const float* __restrict__ bta, bf16* __restrict__ out) {
    long row = blockIdx.x;
    int d = threadIdx.x;
    float v = __bfloat162float(y[row * kD + d]);
    float mu = bsum(v) * (1.f / kD);
    float df = v - mu;
    float var = bsum(df * df) * (1.f / kD);
    out[row * kD + d] = __float2bfloat16(g[d] * df * rsqrtf(var + 1e-5f) + bta[d]);
}
__global__ void featsum_part_k(Scratch* sp) {
    int bi = blockIdx.x, ch = blockIdx.y, d = threadIdx.x;
    int branch = bi >> 3, b = bi & 7;
    const bf16* xp = sp->xp[branch];
    const bf16* ga = sp->ga[branch];
    float s1 = 0.f, s2 = 0.f;
    int q0 = ch * 128;
    for (int q = q0; q < q0 + 128; q++) {
        long o = ((long)(b * kKP + q)) * kD + d;
        s1 += __bfloat162float(xp[o]);
        s2 += __bfloat162float(ga[o]);
    }
    sp->up[(bi * 6 + ch) * 512 + d] = s1;
    sp->up[(bi * 6 + ch) * 512 + 256 + d] = s2;
}
__global__ void featsum_red_k(Scratch* sp) {
    int bi = blockIdx.x, d = threadIdx.x;
    float s = 0.f;
    for (int ch = 0; ch < 6; ch++) s += sp->up[(bi * 6 + ch) * 512 + d];
    sp->u[bi * 512 + d] = s;
}
__global__ void cos_k(const float* __restrict__ u, float* __restrict__ out) {
    int b = blockIdx.x, t = threadIdx.x;
    float a = u[b * 512 + t];
    float c = u[(kB + b) * 512 + t];
    float dot = bsum(a * c);
    float na = bsum(a * a);
    float nc = bsum(c * c);
    if (t == 0)
        out[b] = dot / (fmaxf(sqrtf(na), 1e-8f) * fmaxf(sqrtf(nc), 1e-8f));
}

// ------------------------- host orchestration -------------------------
static void gemm(const bf16* A, int lda, long A2, long Ab, long Ah,
                 const bf16* Bm, int ldb, long B2, long Bb, long Bh,
                 bf16* C, int ldc, long C2, long Cb, long Ch,
                 const bf16* Add, int ldadd, const bf16* Add2, const float* gptr,
                 int M, int N, int K, int ZC, int ZB, int ZH, float alpha, int mode,
                 unsigned zmask = 0, long Aalt = 0, int Malt = 0,
                 long Valt = 0, int zsplit = 1 << 30) {
    int ZT = ZB * ZH;
    if (N % 128 == 0) {
        int sm = (2 * 128 * 40 + 2 * 128 * 40) * 2;
        dim3 g(M / 128, N / 128, ZC * ZT), blk(256);
        cudaFuncSetAttribute(hgemm_k<128>, cudaFuncAttributeMaxDynamicSharedMemorySize, sm);
        hgemm_k<128><<<g, blk, sm>>>(A, lda, A2, Ab, Ah, Bm, ldb, B2, Bb, Bh,
                                     C, ldc, C2, Cb, Ch, Add, ldadd, Add2, gptr,
                                     K, ZH, ZT, alpha, mode, zmask, Aalt, Malt, M,
                                     Valt, zsplit);
    } else {
        int sm = (2 * 128 * 40 + 2 * 64 * 40) * 2;
        dim3 g(M / 128, N / 64, ZC * ZT), blk(256);
        cudaFuncSetAttribute(hgemm_k<64>, cudaFuncAttributeMaxDynamicSharedMemorySize, sm);
        hgemm_k<64><<<g, blk, sm>>>(A, lda, A2, Ab, Ah, Bm, ldb, B2, Bb, Bh,
                                    C, ldc, C2, Cb, Ch, Add, ldadd, Add2, gptr,
                                    K, ZH, ZT, alpha, mode, zmask, Aalt, Malt, M,
                                    Valt, zsplit);
    }
}

extern "C" void kernel_launch(void* const* d_in, const int* in_sizes, int n_in,
                              void* d_out, int out_size) {
    Scratch* sp = nullptr;
    cudaGetSymbolAddress((void**)&sp, SC);

    const float* Wk    = (const float*)d_in[12];
    const float* Wq    = (const float*)d_in[13];
    const float* Wv    = (const float*)d_in[14];
    const float* Wo    = (const float*)d_in[15];
    const float* arel  = (const float*)d_in[16];
    const float* mrel  = (const float*)d_in[17];
    const float* prel  = (const float*)d_in[18];
    const float* skip  = (const float*)d_in[19];
    const float* poolW = (const float*)d_in[20];
    const float* poolA = (const float*)d_in[21];
    const float* poolB = (const float*)d_in[22];
    const float* tWq   = (const float*)d_in[23];
    const float* tWk   = (const float*)d_in[24];
    const float* tWv   = (const float*)d_in[25];
    const float* tWo   = (const float*)d_in[26];
    const float* lng   = (const float*)d_in[27];
    const float* lnb   = (const float*)d_in[28];

    const long T1 = (long)kNI * kD;
    const long KQVB = 3 * LXD;

    pack_all_k<<<(int)((PW + PT + PR + PO + P2 + 255) / 256), 256>>>(
        Wk, Wq, Wv, tWq, tWk, tWv, arel, mrel, Wo, tWo, sp);
    assemble_x_k<<<(int)(2 * LXD / 4 + 255) / 256, 256>>>(
        (const float*)d_in[0], (const float*)d_in[1],
        (const float*)d_in[6], (const float*)d_in[7], sp);

    const int krel_smem = (128 * 72 + 4 * 64 * 72) * 2;
    cudaFuncSetAttribute(krel_k, cudaFuncAttributeMaxDynamicSharedMemorySize, krel_smem);

    bool csr_done = false;

    for (int l = 0; l < 2; l++) {
        for (int dir = 0; dir < 2; dir++) {
            int combo = l * 2 + dir;
            // QKV: z = (branch:2) x (type:2 via zb mask)
            gemm(&sp->x[0][0], kD, LXD, 0, 0,
                 sp->pW + (long)(combo * 2) * 768 * 256, 256, 0, 768 * 256, 0,
                 &sp->kqv[0][0], 768, KQVB, (long)kNI * 768, 0,
                 nullptr, 0, nullptr, nullptr,
                 kNI, 768, kD, 2, 2, 1, 1.f, 0,
                 0x2u, T1, kND);
            // Krel+Vrel: specialized A-reuse kernel
            krel_k<<<dim3(96, 1, 16), 256, krel_smem>>>(sp, combo, dir);
            if (!csr_done) {
                for (int br = 0; br < 2; br++) {
                    const int* e = (const int*)d_in[br * 6 + 2];
                    const int *rc = e, *cc = e + kEC;
                    const int* e2 = (const int*)d_in[br * 6 + 3];
                    const int *ri = e2, *ci = e2 + kEI;
                    const int* e3 = (const int*)d_in[br * 6 + 4];
                    const int *ro = e3, *co = e3 + kEO;
                    const int* e4 = (const int*)d_in[br * 6 + 5];
                    const int *rk = e4, *ck = e4 + kEK;
                    csr_count_k<<<(BB11 + 255) / 256, 256>>>(sp, rc, cc, ri, ci, ro, co, rk, ck);
                    csr_scan_k<<<5, 1024>>>(sp, br);
                    csr_fill_k<<<(BB12 + 255) / 256, 256>>>(sp, br, rc, cc, ri, ci, ro, co, rk, ck);
                }
                csr_done = true;
            }
            hgt_agg_k<<<2 * kNT, 128>>>(sp, dir, prel + (long)(combo * 4) * kH);
            // Wo: z = (branch:2) x (type:2 via zb mask)
            const float* gp = skip + combo * 2;
            if (dir == 0)
                gemm(&sp->agg[0][0], kD, LXD, 0, 0,
                     sp->pWo + (long)(combo * 2) * 65536, 256, 0, 65536, 0,
                     &sp->yF[0][0], kD, LXD, T1, 0, &sp->x[0][0], kD, nullptr, gp,
                     kNI, kD, kD, 2, 2, 1, 1.f, 1,
                     0x2u, T1, kND);
            else
                gemm(&sp->agg[0][0], kD, LXD, 0, 0,
                     sp->pWo + (long)(combo * 2) * 65536, 256, 0, 65536, 0,
                     &sp->x[0][0], kD, LXD, T1, 0, &sp->x[0][0], kD, &sp->yF[0][0], gp,
                     kNI, kD, kD, 2, 2, 1, 1.f, 3,
                     0x2u, T1, kND);
        }
    }

    // pooling (both branches)
    hv_k<<<2 * kNT / 8, 256>>>(sp, poolW);
    gat_score_k<<<(2 * kNT + 255) / 256, 256>>>(sp, poolA, poolB);
    topk_sort_k<<<16, 1024>>>(sp);
    gather_k<<<dim3(kKP, 16), kD>>>(sp);

    // transformer attention (both branches)
    int Mp = kB * kKP;
    long pq = (long)kKP * 768;
    gemm(&sp->xp[0][0], kD, LPD, 0, 0, sp->pTw, 256, 0, 0, 0,
         &sp->qkvp[0][0], 768, 3 * LPD, 0, 0,
         nullptr, 0, nullptr, nullptr, Mp, 768, kD, 2, 1, 1, 1.f, 0);
    gemm(&sp->qkvp[0][0], 768, 3 * LPD, pq, kDH,
         &sp->qkvp[0][0] + 256, 768, 3 * LPD, pq, kDH,
         &sp->S[0][0], kKP, SLEN, (long)kH * kKP * kKP, (long)kKP * kKP,
         nullptr, 0, nullptr, nullptr,
         kKP, kKP, kDH, 2, kB, kH, 0.125f, 0);
    softmax_k<<<2 * kB * kH * kKP, 256>>>(&sp->S[0][0]);
    vtrans_k<<<(int)((2L * kB * kH * 64 * kKP + 255) / 256), 256>>>(sp);
    gemm(&sp->S[0][0], kKP, SLEN, (long)kH * kKP * kKP, (long)kKP * kKP,
         &sp->vT[0][0], kKP, (long)kB * kH * 64 * kKP, (long)kH * 64 * kKP, (long)64 * kKP,
         &sp->oh[0][0], kD, LPD, (long)kKP * kD, kDH,
         nullptr, 0, nullptr, nullptr,
         kKP, kDH, kKP, 2, kB, kH, 1.f, 0);
    gemm(&sp->oh[0][0], kD, LPD, 0, 0, sp->pTwo, 256, 0, 0, 0,
         &sp->yb[0][0], kD, LPD, 0, 0,
         &sp->xp[0][0], kD, nullptr, nullptr, Mp, kD, kD, 2, 1, 1, 1.f, 2);
    ln_k<<<2 * Mp, kD>>>(&sp->yb[0][0], lng, lnb, &sp->ga[0][0]);
    featsum_part_k<<<dim3(16, 6), 256>>>(sp);
    featsum_red_k<<<16, 512>>>(sp);
    cos_k<<<kB, 512>>>(sp->u, (float*)d_out);
}